// round 10
// baseline (speedup 1.0000x reference)
#include <cuda_runtime.h>
#include <cuda_fp16.h>
#include <math.h>

#define SEQ 4096
#define INP 457
#define EMB 2048
#define G4E 8192
#define G4I 1828
#define NCTA 148
#define DCTA 57
#define CROWS 52   // fp16 Whh rows cached in SMEM per encoder CTA

__device__ float g_gx[(size_t)SEQ * G4E];     // Wih@x + biases, per timestep
__device__ float g_wihT[(size_t)INP * G4E];   // enc_Wih transposed
__device__ __half g_whh_h[(size_t)G4E * EMB]; // enc_Whh in fp16
__device__ float g_weff[(size_t)G4I * INP];   // (dec_Wih+dec_Whh)@dec_Whr
__device__ float g_g0[G4I];                   // decoder step-0 gates
__device__ float g_h[EMB];                    // final encoder hidden (for dec_g0)

// Data-as-flag exchange lines: one 128B line per CTA per parity.
// Words [0..cnt) = h chunk (float bits), word 31 = tag (step sequence).
__device__ volatile unsigned g_hl_enc[2][NCTA * 32];
__device__ volatile unsigned g_hl_dec[2][DCTA * 32];

__device__ __forceinline__ float sigf(float x) { return 1.0f / (1.0f + expf(-x)); }

// fp16 conversion of enc_Whh + tag init (fused, launch #0).
__global__ void conv_init_kernel(const float* __restrict__ whh) {
  size_t i = (size_t)blockIdx.x * blockDim.x + threadIdx.x;
  size_t i4 = i * 4;
  float4 v = *(const float4*)(whh + i4);
  __half2* dst = (__half2*)(g_whh_h + i4);
  dst[0] = __floats2half2_rn(v.x, v.y);
  dst[1] = __floats2half2_rn(v.z, v.w);
  if (i < NCTA * 32) { g_hl_enc[0][i] = 0u; g_hl_enc[1][i] = 0u; }
  if (i < DCTA * 32) { g_hl_dec[0][i] = 0u; g_hl_dec[1][i] = 0u; }
}

// Transpose enc_Wih [8192][457] -> g_wihT [457][8192]
__global__ void tr_kernel(const float* __restrict__ in) {
  __shared__ float tile[32][33];
  int r0 = blockIdx.x * 32, c0 = blockIdx.y * 32;
  int x = threadIdx.x;
  for (int y = threadIdx.y; y < 32; y += 8) {
    int c = c0 + x;
    if (c < INP) tile[y][x] = in[(size_t)(r0 + y) * INP + c];
  }
  __syncthreads();
  for (int y = threadIdx.y; y < 32; y += 8) {
    int c = c0 + y;
    if (c < INP) g_wihT[(size_t)c * G4E + r0 + x] = tile[x][y];
  }
}

// Gx[t][r] = sum_k x[t][k]*Wih[r][k] + bih[r] + bhh[r]
__global__ void __launch_bounds__(256) gx_kernel(const float* __restrict__ x,
                                                 const float* __restrict__ bih,
                                                 const float* __restrict__ bhh) {
  __shared__ float xs[INP * 20];
  const int tid = threadIdx.x;
  const int rb = blockIdx.x * 256, tb = blockIdx.y * 16;
  for (int i = tid; i < 16 * INP; i += 256) {
    int tt = i / INP, k = i - tt * INP;
    xs[k * 20 + tt] = x[(size_t)(tb + tt) * INP + k];
  }
  __syncthreads();
  const int r = rb + tid;
  float acc[16];
#pragma unroll
  for (int j = 0; j < 16; j++) acc[j] = 0.0f;
  for (int k = 0; k < INP; k++) {
    float w = g_wihT[(size_t)k * G4E + r];
    const float4* xv = (const float4*)(xs + k * 20);
    float4 a = xv[0], b = xv[1], c = xv[2], d = xv[3];
    acc[0]  += w * a.x; acc[1]  += w * a.y; acc[2]  += w * a.z; acc[3]  += w * a.w;
    acc[4]  += w * b.x; acc[5]  += w * b.y; acc[6]  += w * b.z; acc[7]  += w * b.w;
    acc[8]  += w * c.x; acc[9]  += w * c.y; acc[10] += w * c.z; acc[11] += w * c.w;
    acc[12] += w * d.x; acc[13] += w * d.y; acc[14] += w * d.z; acc[15] += w * d.w;
  }
  float bsum = bih[r] + bhh[r];
#pragma unroll
  for (int j = 0; j < 16; j++) g_gx[(size_t)(tb + j) * G4E + r] = acc[j] + bsum;
}

// W_eff[r][j] = sum_m (dWih[r][m]+dWhh[r][m]) * dWhr[m][j]
__global__ void __launch_bounds__(128) weff_kernel(const float* __restrict__ dwih,
                                                   const float* __restrict__ dwhh,
                                                   const float* __restrict__ whr) {
  __shared__ float wcs[8 * 128];
  const int tid = threadIdx.x;
  const int r0 = blockIdx.x * 8;
  float acc[8][4];
#pragma unroll
  for (int i = 0; i < 8; i++)
#pragma unroll
    for (int j = 0; j < 4; j++) acc[i][j] = 0.0f;

  for (int kb = 0; kb < EMB; kb += 128) {
    __syncthreads();
#pragma unroll
    for (int i = 0; i < 8; i++) {
      int row = r0 + i; if (row > G4I - 1) row = G4I - 1;
      size_t idx = (size_t)row * EMB + kb + tid;
      wcs[i * 128 + tid] = dwih[idx] + dwhh[idx];
    }
    __syncthreads();
#pragma unroll 4
    for (int kk = 0; kk < 128; kk++) {
      const float* wrow = whr + (size_t)(kb + kk) * INP;
      float v0 = wrow[tid];
      float v1 = wrow[tid + 128];
      float v2 = wrow[tid + 256];
      float v3 = (tid < 73) ? wrow[tid + 384] : 0.0f;
#pragma unroll
      for (int i = 0; i < 8; i++) {
        float w = wcs[i * 128 + kk];
        acc[i][0] += w * v0; acc[i][1] += w * v1;
        acc[i][2] += w * v2; acc[i][3] += w * v3;
      }
    }
  }
#pragma unroll
  for (int i = 0; i < 8; i++) {
    int row = r0 + i;
    if (row < G4I) {
      size_t rb = (size_t)row * INP;
      g_weff[rb + tid]       = acc[i][0];
      g_weff[rb + tid + 128] = acc[i][1];
      g_weff[rb + tid + 256] = acc[i][2];
      if (tid < 73) g_weff[rb + tid + 384] = acc[i][3];
    }
  }
}

// Persistent encoder, fp16 weights, data-as-flag h exchange.
extern __shared__ __half esmh[];
__global__ void __launch_bounds__(256, 1) enc_kernel(const float* __restrict__ whhf) {
  const int tid = threadIdx.x, wid = tid >> 5, lane = tid & 31, b = blockIdx.x;
  const int cnt   = (b < 124) ? 14 : 13;
  const int start = (b < 124) ? 14 * b : 1736 + 13 * (b - 124);
  const int nrows = 4 * cnt;
  __half* ws   = esmh;                                  // CROWS * 2048 halfs
  float*  hs   = (float*)(esmh + (size_t)CROWS * EMB);  // 2048 floats
  float*  gsum = hs + EMB;                              // 64 floats
  float4* hs4  = (float4*)hs;

  for (int idx = tid; idx < CROWS * EMB; idx += 256) {
    int i = idx >> 11, k = idx & 2047;
    int e = start + (i >> 2), q = i & 3;
    ws[idx] = g_whh_h[((size_t)(q << 11) + e) * EMB + k];
  }

  // Pre-publish h0 = 0 into parity 0 with tag 1.
  if (tid < cnt) g_hl_enc[0][b * 32 + tid] = 0u;
  __threadfence();
  __syncthreads();
  if (tid == 0) g_hl_enc[0][b * 32 + 31] = 1u;

  float c = 0.0f;
  for (int t = 0; t < SEQ; t++) {
    const int par = t & 1;
    float gx0 = 0.f, gx1 = 0.f, gx2 = 0.f, gx3 = 0.f;
    if (tid < cnt) {
      size_t base = (size_t)t * G4E + start + tid;
      gx0 = __ldcg(&g_gx[base]);
      gx1 = __ldcg(&g_gx[base + 2048]);
      gx2 = __ldcg(&g_gx[base + 4096]);
      gx3 = __ldcg(&g_gx[base + 6144]);
    }
    // Consume: thread j polls producer j's tag, then reads its h chunk.
    if (tid < NCTA) {
      const volatile unsigned* ln = &g_hl_enc[par][tid * 32];
      while (ln[31] < (unsigned)(t + 1)) {}
      __threadfence();
      const uint4* d4 = (const uint4*)(const void*)ln;
      uint4 a = __ldcg(d4), bq = __ldcg(d4 + 1), cq = __ldcg(d4 + 2), dq = __ldcg(d4 + 3);
      int cj = (tid < 124) ? 14 : 13;
      int sj = (tid < 124) ? 14 * tid : 1736 + 13 * (tid - 124);
      float* hd = hs + sj;
      hd[0]  = __uint_as_float(a.x);  hd[1]  = __uint_as_float(a.y);
      hd[2]  = __uint_as_float(a.z);  hd[3]  = __uint_as_float(a.w);
      hd[4]  = __uint_as_float(bq.x); hd[5]  = __uint_as_float(bq.y);
      hd[6]  = __uint_as_float(bq.z); hd[7]  = __uint_as_float(bq.w);
      hd[8]  = __uint_as_float(cq.x); hd[9]  = __uint_as_float(cq.y);
      hd[10] = __uint_as_float(cq.z); hd[11] = __uint_as_float(cq.w);
      hd[12] = __uint_as_float(dq.x);
      if (cj == 14) hd[13] = __uint_as_float(dq.y);
    }
    __syncthreads();

    float4 h4[16];
#pragma unroll
    for (int j = 0; j < 16; j++) h4[j] = hs4[lane + 32 * j];

#pragma unroll 1
    for (int k = 0; k < 7; k++) {
      int i = wid + 8 * k;
      if (i >= nrows) break;  // warp-uniform
      float sum = 0.0f;
      if (i < CROWS) {
        const uint2* wr = (const uint2*)(ws + (size_t)i * EMB);
#pragma unroll
        for (int j = 0; j < 16; j++) {
          uint2 wp = wr[lane + 32 * j];
          float2 a = __half22float2(*(__half2*)&wp.x);
          float2 bq = __half22float2(*(__half2*)&wp.y);
          float4 hv = h4[j];
          sum += a.x * hv.x; sum += a.y * hv.y;
          sum += bq.x * hv.z; sum += bq.y * hv.w;
        }
      } else {
        int e = start + (i >> 2), q = i & 3;
        const uint2* wr = (const uint2*)(g_whh_h + ((size_t)(q << 11) + e) * EMB);
#pragma unroll
        for (int j = 0; j < 16; j++) {
          uint2 wp = __ldcg(wr + lane + 32 * j);
          float2 a = __half22float2(*(__half2*)&wp.x);
          float2 bq = __half22float2(*(__half2*)&wp.y);
          float4 hv = h4[j];
          sum += a.x * hv.x; sum += a.y * hv.y;
          sum += bq.x * hv.z; sum += bq.y * hv.w;
        }
      }
#pragma unroll
      for (int o = 16; o; o >>= 1) sum += __shfl_xor_sync(0xffffffffu, sum, o);
      if (lane == 0) gsum[i] = sum;
    }
    __syncthreads();

    if (tid < cnt) {
      float gi = gsum[4 * tid + 0] + gx0;
      float gf = gsum[4 * tid + 1] + gx1;
      float gg = gsum[4 * tid + 2] + gx2;
      float go = gsum[4 * tid + 3] + gx3;
      c = sigf(gf) * c + sigf(gi) * tanhf(gg);
      float hnew = sigf(go) * tanhf(c);
      g_hl_enc[par ^ 1][b * 32 + tid] = __float_as_uint(hnew);
      if (t == SEQ - 1) g_h[start + tid] = hnew;
      __threadfence();
    }
    __syncthreads();
    if (tid == 0) g_hl_enc[par ^ 1][b * 32 + 31] = (unsigned)(t + 2);
  }
}

// g0[r] = dec_Wih[r] . h_enc + bih[r] + bhh[r]
__global__ void dec_g0_kernel(const float* __restrict__ dwih,
                              const float* __restrict__ bih,
                              const float* __restrict__ bhh) {
  int wid = threadIdx.x >> 5, lane = threadIdx.x & 31;
  int row = blockIdx.x * 8 + wid;
  if (row >= G4I) return;
  const float4* w = (const float4*)(dwih + (size_t)row * EMB);
  const float4* h = (const float4*)g_h;
  float sum = 0.0f;
  for (int k = lane; k < EMB / 4; k += 32) {
    float4 a = w[k], b = h[k];
    sum += a.x * b.x + a.y * b.y + a.z * b.z + a.w * b.w;
  }
#pragma unroll
  for (int o = 16; o; o >>= 1) sum += __shfl_xor_sync(0xffffffffu, sum, o);
  if (lane == 0) g_g0[row] = sum + bih[row] + bhh[row];
}

// Persistent decoder: 57 CTAs, data-as-flag h_raw exchange.
// CTA b owns elems [8b, 8b+cnt), cnt=8 (9 for b=56); nrows=4*cnt rows in SMEM.
__global__ void __launch_bounds__(256, 1) dec_kernel(const float* __restrict__ bih,
                                                     const float* __restrict__ bhh,
                                                     float* __restrict__ out) {
  float* ws   = (float*)esmh;        // 36*INP max
  float* hrs  = ws + 36 * INP;       // INP
  float* bs   = hrs + INP;           // 36
  float* gsum = bs + 36;             // 36
  const int tid = threadIdx.x, wid = tid >> 5, lane = tid & 31, b = blockIdx.x;
  const int cnt = (b == 56) ? 9 : 8;
  const int e0 = 8 * b;
  const int nrows = 4 * cnt;

  for (int idx = tid; idx < nrows * INP; idx += 256) {
    int l = idx / INP, k = idx - l * INP;
    int q = l & 3, el = l >> 2;
    ws[l * INP + k] = g_weff[(size_t)(q * INP + e0 + el) * INP + k];
  }
  if (tid < nrows) {
    int q = tid & 3, el = tid >> 2;
    bs[tid] = bih[q * INP + e0 + el] + bhh[q * INP + e0 + el];
  }
  // Pre-publish h_raw_0 = 0 into parity 0 with tag 1.
  if (tid < cnt) g_hl_dec[0][b * 32 + tid] = 0u;
  __threadfence();
  __syncthreads();
  if (tid == 0) g_hl_dec[0][b * 32 + 31] = 1u;

  float c = 0.0f;
  for (int t = 0; t < SEQ; t++) {
    const int par = t & 1;
    // Consume (also the inter-CTA sync).
    if (tid < DCTA) {
      const volatile unsigned* ln = &g_hl_dec[par][tid * 32];
      while (ln[31] < (unsigned)(t + 1)) {}
      __threadfence();
      const uint4* d4 = (const uint4*)(const void*)ln;
      uint4 a = __ldcg(d4), bq = __ldcg(d4 + 1);
      unsigned w8 = __ldcg((const unsigned*)(const void*)(ln + 8));
      float* hd = hrs + 8 * tid;
      hd[0] = __uint_as_float(a.x);  hd[1] = __uint_as_float(a.y);
      hd[2] = __uint_as_float(a.z);  hd[3] = __uint_as_float(a.w);
      hd[4] = __uint_as_float(bq.x); hd[5] = __uint_as_float(bq.y);
      hd[6] = __uint_as_float(bq.z); hd[7] = __uint_as_float(bq.w);
      if (tid == 56) hd[8] = __uint_as_float(w8);
    }
    __syncthreads();

    if (t > 0) {
#pragma unroll 1
      for (int k8 = 0; k8 < 5; k8++) {
        int l = wid + 8 * k8;
        if (l >= nrows) break;  // warp-uniform
        const float* wr = ws + l * INP;
        float sum = 0.0f;
#pragma unroll 5
        for (int k = lane; k < INP; k += 32) sum += wr[k] * hrs[k];
#pragma unroll
        for (int o = 16; o; o >>= 1) sum += __shfl_xor_sync(0xffffffffu, sum, o);
        if (lane == 0) gsum[l] = sum;
      }
      __syncthreads();
    }
    if (tid < cnt) {
      int e = e0 + tid;
      float gi, gf, gg, go;
      if (t == 0) {
        gi = g_g0[e]; gf = g_g0[INP + e]; gg = g_g0[2 * INP + e]; go = g_g0[3 * INP + e];
      } else {
        gi = gsum[4 * tid + 0] + bs[4 * tid + 0];
        gf = gsum[4 * tid + 1] + bs[4 * tid + 1];
        gg = gsum[4 * tid + 2] + bs[4 * tid + 2];
        go = gsum[4 * tid + 3] + bs[4 * tid + 3];
      }
      c = sigf(gf) * c + sigf(gi) * tanhf(gg);
      out[(size_t)(SEQ - 1 - t) * INP + e] = c;
      g_hl_dec[par ^ 1][b * 32 + tid] = __float_as_uint(sigf(go) * tanhf(c));
      __threadfence();
    }
    __syncthreads();
    if (tid == 0) g_hl_dec[par ^ 1][b * 32 + 31] = (unsigned)(t + 2);
  }
}

// In-place row softmax over out[4096][457]
__global__ void softmax_kernel(float* __restrict__ out) {
  __shared__ float red[32];
  const int t = blockIdx.x, tid = threadIdx.x, lane = tid & 31, wid = tid >> 5;
  float v = (tid < INP) ? out[(size_t)t * INP + tid] : -1e30f;
  float m = v;
#pragma unroll
  for (int o = 16; o; o >>= 1) m = fmaxf(m, __shfl_xor_sync(0xffffffffu, m, o));
  if (lane == 0) red[wid] = m;
  __syncthreads();
  m = -1e30f;
  for (int i = 0; i < 16; i++) m = fmaxf(m, red[i]);
  __syncthreads();
  float e = (tid < INP) ? expf(v - m) : 0.0f;
  float sum = e;
#pragma unroll
  for (int o = 16; o; o >>= 1) sum += __shfl_xor_sync(0xffffffffu, sum, o);
  if (lane == 0) red[wid] = sum;
  __syncthreads();
  sum = 0.0f;
  for (int i = 0; i < 16; i++) sum += red[i];
  if (tid < INP) out[(size_t)t * INP + tid] = e / sum;
}

extern "C" void kernel_launch(void* const* d_in, const int* in_sizes, int n_in,
                              void* d_out, int out_size) {
  const float* x    = (const float*)d_in[0];
  const float* eWih = (const float*)d_in[1];
  const float* eWhh = (const float*)d_in[2];
  const float* ebih = (const float*)d_in[3];
  const float* ebhh = (const float*)d_in[4];
  const float* dWih = (const float*)d_in[5];
  const float* dWhh = (const float*)d_in[6];
  const float* dbih = (const float*)d_in[7];
  const float* dbhh = (const float*)d_in[8];
  const float* dWhr = (const float*)d_in[9];
  float* out = (float*)d_out;

  const int enc_smem = CROWS * EMB * 2 + (EMB + 64) * 4;       // 221,440 B
  const int dec_smem = (36 * INP + INP + 72) * 4 + 64;         // ~68 KB
  cudaFuncSetAttribute(enc_kernel, cudaFuncAttributeMaxDynamicSharedMemorySize, enc_smem);
  cudaFuncSetAttribute(dec_kernel, cudaFuncAttributeMaxDynamicSharedMemorySize, dec_smem);

  conv_init_kernel<<<16384, 256>>>(eWhh);
  tr_kernel<<<dim3(256, 15), dim3(32, 8)>>>(eWih);
  gx_kernel<<<dim3(32, 256), 256>>>(x, ebih, ebhh);
  enc_kernel<<<NCTA, 256, enc_smem>>>(eWhh);
  weff_kernel<<<229, 128>>>(dWih, dWhh, dWhr);
  dec_g0_kernel<<<229, 256>>>(dWih, dbih, dbhh);
  dec_kernel<<<DCTA, 256, dec_smem>>>(dbih, dbhh, out);
  softmax_kernel<<<SEQ, 512>>>(out);
}